// round 1
// baseline (speedup 1.0000x reference)
#include <cuda_runtime.h>
#include <cuda_bf16.h>

// MySoftBCELoss: B=1048576 rows, C=32 classes, fp32.
// per-element: pred=clamp(sigmoid(x),eps,1-eps); lp=log(pred); l1p=log(1-pred)
//   lp  = x - softplus(x)   (clamped below at log(EPS))
//   l1p =   - softplus(x)   (clamped below at log(EPS))
// softplus(x) = max(x,0) + log1p(exp(-|x|)), all in FFMA (no MUFU).

#define BLOCK 256
#define ROWS_TOTAL 1048576
#define GRID_MAIN (ROWS_TOTAL / BLOCK)   // 4096

__device__ float g_partials[GRID_MAIN];

#define LOG_EPS (-16.11809565095832f)    // log(1e-7)

// exp(-u) for u >= 0, FFMA-only (no MUFU)
__device__ __forceinline__ float exp_neg_fast(float u) {
    float y = fmaxf(u * -1.4426950408889634f, -24.0f);  // log2(e)
    float r = y + 12582912.0f;                          // round-to-nearest int
    float f = y - (r - 12582912.0f);                    // f in [-0.5, 0.5]
    // 2^f poly (Taylor/minimax hybrid, err ~1e-7)
    float p = 1.535336e-4f;
    p = fmaf(p, f, 1.339887e-3f);
    p = fmaf(p, f, 9.618437e-3f);
    p = fmaf(p, f, 5.550332e-2f);
    p = fmaf(p, f, 2.402265e-1f);
    p = fmaf(p, f, 6.931472e-1f);
    p = fmaf(p, f, 1.0f);
    // scale by 2^i via exponent bits: bits(r) = 0x4B400000 + i
    int ib = __float_as_int(r);
    float scale = __int_as_float((ib - 0x4B3FFF81) << 23);  // (i+127)<<23
    return p * scale;
}

// log1p(t) for t in [0, 1] — Hastings / A&S 4.1.44 degree-8, |err| <= 3e-8
__device__ __forceinline__ float log1p_unit(float t) {
    float q = -0.0064535442f;
    q = fmaf(q, t, 0.0360884937f);
    q = fmaf(q, t, -0.0953293897f);
    q = fmaf(q, t, 0.1676540711f);
    q = fmaf(q, t, -0.2407338084f);
    q = fmaf(q, t, 0.3317990258f);
    q = fmaf(q, t, -0.4998741238f);
    q = fmaf(q, t, 0.9999964239f);
    return q * t;
}

__global__ void __launch_bounds__(BLOCK) softbce_main(
    const float4* __restrict__ logits4,
    const float4* __restrict__ target4)
{
    const int row = blockIdx.x * BLOCK + threadIdx.x;
    const float4* lrow = logits4 + (size_t)row * 8;
    const float4* trow = target4 + (size_t)row * 8;

    float sum0 = 0.0f;        // sum over classes of t*lp + (1-t)*l1p
    float tmax = -1.0f;       // running argmax of target (strict >: first occurrence)
    int   cmax = 0;
    float lpmax = 0.0f;       // lp at argmax column
    float l1p0 = 0.0f;        // l1p at column 0

    #pragma unroll
    for (int j = 0; j < 8; j++) {
        float4 lv = __ldg(lrow + j);
        float4 tv = __ldg(trow + j);
        float xs[4] = {lv.x, lv.y, lv.z, lv.w};
        float ts[4] = {tv.x, tv.y, tv.z, tv.w};
        #pragma unroll
        for (int k = 0; k < 4; k++) {
            float x = xs[k];
            float t = ts[k];
            float u  = fabsf(x);
            float L0 = log1p_unit(exp_neg_fast(u));   // log1p(exp(-|x|))
            float L  = fmaxf(x, 0.0f) + L0;           // softplus(x)
            float lp  = fmaxf(x - L, LOG_EPS);
            float l1p = fmaxf(-L,    LOG_EPS);
            // t*lp + (1-t)*l1p
            sum0 += fmaf(t, lp - l1p, l1p);
            int c = 4 * j + k;
            if (c == 0) l1p0 = l1p;
            if (t > tmax) { tmax = t; cmax = c; lpmax = lp; }
        }
    }

    // per-row loss (NEG_WEIGHT = 1)
    float loss = (cmax == 0) ? (sum0 * (1.0f / 32.0f))
                             : fmaf(tmax, lpmax, l1p0);

    // deterministic block tree-reduce
    __shared__ float sdata[BLOCK];
    sdata[threadIdx.x] = loss;
    __syncthreads();
    #pragma unroll
    for (int s = BLOCK / 2; s > 0; s >>= 1) {
        if (threadIdx.x < s) sdata[threadIdx.x] += sdata[threadIdx.x + s];
        __syncthreads();
    }
    if (threadIdx.x == 0) g_partials[blockIdx.x] = sdata[0];
}

__global__ void __launch_bounds__(1024) softbce_reduce(float* __restrict__ out)
{
    __shared__ float sdata[1024];
    float s = 0.0f;
    #pragma unroll
    for (int i = threadIdx.x; i < GRID_MAIN; i += 1024)
        s += g_partials[i];
    sdata[threadIdx.x] = s;
    __syncthreads();
    #pragma unroll
    for (int st = 512; st > 0; st >>= 1) {
        if (threadIdx.x < st) sdata[threadIdx.x] += sdata[threadIdx.x + st];
        __syncthreads();
    }
    if (threadIdx.x == 0)
        out[0] = -sdata[0] * (1.0f / (float)ROWS_TOTAL);
}

extern "C" void kernel_launch(void* const* d_in, const int* in_sizes, int n_in,
                              void* d_out, int out_size)
{
    const float4* logits = (const float4*)d_in[0];
    const float4* target = (const float4*)d_in[1];
    float* out = (float*)d_out;

    softbce_main<<<GRID_MAIN, BLOCK>>>(logits, target);
    softbce_reduce<<<1, 1024>>>(out);
}

// round 2
// speedup vs baseline: 1.6238x; 1.6238x over previous
#include <cuda_runtime.h>
#include <cuda_bf16.h>

// MySoftBCELoss: B=1048576 rows, C=32 classes, fp32 -> scalar.
//   lp  = log(clamp(sigmoid(x)))   = x - softplus(x)   (clamped at log(eps))
//   l1p = log(clamp(1-sigmoid(x))) =   - softplus(x)   (clamped at log(eps))
//   softplus(x) = max(x,0) + log1p(exp(-|x|))  -> MUFU ex2/lg2 path
//
// Strategy: smem-staged transpose for coalesced HBM loads, MUFU transcendentals
// (off the FMA pipe), single kernel with last-block-done final reduction.

#define BLOCK 128
#define ROWS_TOTAL 1048576
#define GRID_MAIN (ROWS_TOTAL / BLOCK)   // 8192
#define NCLS 32
#define PITCH 33                          // padded row pitch (floats), conflict-free

#define LOG_EPS (-16.11809565095832f)     // log(1e-7)

__device__ float g_partials[GRID_MAIN];
__device__ int   g_count = 0;

__global__ void __launch_bounds__(BLOCK) softbce_fused(
    const float4* __restrict__ logits4,
    const float4* __restrict__ target4,
    float* __restrict__ out)
{
    __shared__ float sL[BLOCK * PITCH];   // 128*33*4 = 16896 B
    __shared__ float sT[BLOCK * PITCH];

    const int tid = threadIdx.x;
    const size_t base4 = (size_t)blockIdx.x * BLOCK * (NCLS / 4);  // float4 base

    // ---- Phase 1: coalesced gmem -> padded smem (both tensors) ----
    #pragma unroll
    for (int i = tid; i < BLOCK * (NCLS / 4); i += BLOCK) {
        float4 lv = __ldg(logits4 + base4 + i);
        float4 tv = __ldg(target4 + base4 + i);
        int row = i >> 3;           // /8 float4 per row
        int q   = i & 7;
        int sb  = row * PITCH + q * 4;
        sL[sb + 0] = lv.x; sL[sb + 1] = lv.y; sL[sb + 2] = lv.z; sL[sb + 3] = lv.w;
        sT[sb + 0] = tv.x; sT[sb + 1] = tv.y; sT[sb + 2] = tv.z; sT[sb + 3] = tv.w;
    }
    __syncthreads();

    // ---- Phase 2: one row per thread, MUFU softplus ----
    const float* lrow = sL + tid * PITCH;
    const float* trow = sT + tid * PITCH;

    float sum0  = 0.0f;   // full soft-BCE row sum
    float tmax  = -1.0f;  // argmax(target) tracking, strict > => first occurrence
    int   cmax  = 0;
    float lpmax = 0.0f;
    float l1p0  = 0.0f;

    #pragma unroll
    for (int c = 0; c < NCLS; c++) {
        float x = lrow[c];
        float t = trow[c];
        float u = fabsf(x);
        float e = __expf(-u);                 // FMUL + MUFU.EX2
        float s0 = __logf(1.0f + e);          // FADD + MUFU.LG2 + FMUL
        float L  = fmaxf(x, 0.0f) + s0;       // softplus(x)
        float lp  = fmaxf(x - L, LOG_EPS);
        float l1p = fmaxf(-L,    LOG_EPS);
        sum0 += fmaf(t, lp - l1p, l1p);       // t*lp + (1-t)*l1p
        if (c == 0) l1p0 = l1p;
        if (t > tmax) { tmax = t; cmax = c; lpmax = lp; }
    }

    float loss = (cmax == 0) ? (sum0 * (1.0f / (float)NCLS))
                             : fmaf(tmax, lpmax, l1p0);

    // ---- Block reduction: warp shfl then cross-warp ----
    #pragma unroll
    for (int o = 16; o > 0; o >>= 1)
        loss += __shfl_xor_sync(0xFFFFFFFFu, loss, o);

    __shared__ float warp_sums[BLOCK / 32];
    if ((tid & 31) == 0) warp_sums[tid >> 5] = loss;
    __syncthreads();

    __shared__ bool is_last;
    if (tid == 0) {
        float b = warp_sums[0];
        #pragma unroll
        for (int w = 1; w < BLOCK / 32; w++) b += warp_sums[w];
        g_partials[blockIdx.x] = b;
        __threadfence();
        int prev = atomicAdd(&g_count, 1);
        is_last = (prev == GRID_MAIN - 1);
    }
    __syncthreads();

    // ---- Last block: deterministic final reduce ----
    if (is_last) {
        float s = 0.0f;
        #pragma unroll
        for (int i = tid; i < GRID_MAIN; i += BLOCK)
            s += g_partials[i];
        #pragma unroll
        for (int o = 16; o > 0; o >>= 1)
            s += __shfl_xor_sync(0xFFFFFFFFu, s, o);
        if ((tid & 31) == 0) warp_sums[tid >> 5] = s;
        __syncthreads();
        if (tid == 0) {
            float total = warp_sums[0];
            #pragma unroll
            for (int w = 1; w < BLOCK / 32; w++) total += warp_sums[w];
            out[0] = -total * (1.0f / (float)ROWS_TOTAL);
            g_count = 0;   // reset for next graph replay
        }
    }
}

extern "C" void kernel_launch(void* const* d_in, const int* in_sizes, int n_in,
                              void* d_out, int out_size)
{
    const float4* logits = (const float4*)d_in[0];
    const float4* target = (const float4*)d_in[1];
    float* out = (float*)d_out;

    softbce_fused<<<GRID_MAIN, BLOCK>>>(logits, target, out);
}